// round 10
// baseline (speedup 1.0000x reference)
#include <cuda_runtime.h>
#include <cuda_bf16.h>
#include <math.h>
#include <stdint.h>

#define N_NODES 50000
#define N_EDGES 400000
#define D 128
#define H 256
#define EATTR 64
#define XW 160
#define LN_EPS 1e-5f
#define SLOPE 0.01f

__device__ float g_P0[(size_t)N_NODES * H];
__device__ float g_P1[(size_t)N_NODES * H];
__device__ float g_acol[N_NODES];
__device__ float g_arow[N_NODES];
__device__ float g_expv[N_EDGES];
__device__ int   g_elist0[N_EDGES];
__device__ int   g_elist1[N_EDGES];
__device__ float g_flow[(size_t)N_NODES * 256];
__device__ float g_U[(size_t)N_NODES * 128];
__device__ float g_dirsum[2];
__device__ int   g_ecnt[2];

__device__ __forceinline__ void split2(float v0, float v1, uint32_t& hi, uint32_t& lo) {
    __nv_bfloat16 h0 = __float2bfloat16(v0), h1 = __float2bfloat16(v1);
    __nv_bfloat16 l0 = __float2bfloat16(v0 - __bfloat162float(h0));
    __nv_bfloat16 l1 = __float2bfloat16(v1 - __bfloat162float(h1));
    hi = ((uint32_t)__bfloat16_as_ushort(h1) << 16) | __bfloat16_as_ushort(h0);
    lo = ((uint32_t)__bfloat16_as_ushort(l1) << 16) | __bfloat16_as_ushort(l0);
}

__device__ __forceinline__ void mma_bf16(float* c, const uint4& a, const uint2& b) {
    asm volatile(
        "mma.sync.aligned.m16n8k16.row.col.f32.bf16.bf16.f32 "
        "{%0,%1,%2,%3}, {%4,%5,%6,%7}, {%8,%9}, {%0,%1,%2,%3};\n"
        : "+f"(c[0]), "+f"(c[1]), "+f"(c[2]), "+f"(c[3])
        : "r"(a.x), "r"(a.y), "r"(a.z), "r"(a.w), "r"(b.x), "r"(b.y));
}

// ---------------- prologue ----------------
__global__ void k_init_att(const float* __restrict__ x, const float* __restrict__ w_att) {
    size_t i = (size_t)blockIdx.x * blockDim.x + threadIdx.x;
    size_t n4 = (size_t)N_NODES * 256 / 4;
    if (i < n4) reinterpret_cast<float4*>(g_flow)[i] = make_float4(0.f, 0.f, 0.f, 0.f);
    if (i == 0) { g_dirsum[0] = 0.f; g_dirsum[1] = 0.f; g_ecnt[0] = 0; g_ecnt[1] = 0; }
    int gw = (int)(i >> 5);
    int lane = threadIdx.x & 31;
    if (gw < N_NODES) {
        const float* xr = x + (size_t)gw * XW;
        float s0 = 0.f, s1 = 0.f;
        #pragma unroll
        for (int k = lane; k < 128; k += 32) {
            float v = xr[k];
            s0 += v * w_att[k]; s1 += v * w_att[128 + k];
        }
        #pragma unroll
        for (int o = 16; o; o >>= 1) {
            s0 += __shfl_xor_sync(0xffffffffu, s0, o);
            s1 += __shfl_xor_sync(0xffffffffu, s1, o);
        }
        if (lane == 0) { g_acol[gw] = s0; g_arow[gw] = s1; }
    }
}

__global__ void k_sumexp(const int* __restrict__ ei, const float* __restrict__ b_att) {
    __shared__ int c0, c1, base0, base1;
    __shared__ float rs0[8], rs1[8];
    if (threadIdx.x == 0) { c0 = 0; c1 = 0; }
    __syncthreads();
    int e = blockIdx.x * blockDim.x + threadIdx.x;
    int dir = -1, pos = 0;
    float ex = 0.f;
    if (e < N_EDGES) {
        int r = ei[e], c = ei[N_EDGES + e];
        if (r < c) dir = 0; else if (r > c) dir = 1;
        if (dir >= 0) {
            float z = g_acol[c] + g_arow[r] + b_att[0];
            float lg = z > 0.f ? z : SLOPE * z;
            ex = expf(lg);
            pos = atomicAdd(dir ? &c1 : &c0, 1);
        }
        g_expv[e] = ex;
    }
    float v0 = (dir == 0) ? ex : 0.f;
    float v1 = (dir == 1) ? ex : 0.f;
    #pragma unroll
    for (int o = 16; o; o >>= 1) {
        v0 += __shfl_xor_sync(0xffffffffu, v0, o);
        v1 += __shfl_xor_sync(0xffffffffu, v1, o);
    }
    int w = threadIdx.x >> 5, l = threadIdx.x & 31;
    if (l == 0) { rs0[w] = v0; rs1[w] = v1; }
    __syncthreads();
    if (threadIdx.x == 0) {
        float t0 = 0.f, t1 = 0.f;
        for (int k = 0; k < 8; k++) { t0 += rs0[k]; t1 += rs1[k]; }
        if (t0 != 0.f) atomicAdd(&g_dirsum[0], t0);
        if (t1 != 0.f) atomicAdd(&g_dirsum[1], t1);
        base0 = c0 ? atomicAdd(&g_ecnt[0], c0) : 0;
        base1 = c1 ? atomicAdd(&g_ecnt[1], c1) : 0;
    }
    __syncthreads();
    if (dir == 0) g_elist0[base0 + pos] = e;
    else if (dir == 1) g_elist1[base1 + pos] = e;
}

// ---------------- node precompute P = xn @ W1top (dir per CTA) ----------------
#define NM_AH 0
#define NM_AL 16384
#define NM_WH 32768
#define NM_WL 98304
#define SMEM_NM 163840

__global__ void __launch_bounds__(256, 1) k_node_mma(
    const float* __restrict__ x, const float* __restrict__ w0, const float* __restrict__ w1)
{
    extern __shared__ unsigned char sm[];
    int tid = threadIdx.x;
    int lane = tid & 31, wid = tid >> 5;
    int slot = wid & 3, nh = wid >> 2;
    int gid = lane >> 2, tig = lane & 3;
    int d  = blockIdx.x / 148;
    int b0 = blockIdx.x % 148;

    const float* W = d ? w1 : w0;
    float* P = d ? g_P1 : g_P0;
    for (int idx = tid; idx < 16384; idx += 256) {
        int k2i = idx >> 8, n = idx & 255;
        int k = 2 * k2i;
        float v0 = W[(size_t)k * H + n], v1 = W[(size_t)(k + 1) * H + n];
        uint32_t hi, lo; split2(v0, v1, hi, lo);
        int gn = n >> 3, ks = k >> 4;
        int lane_t = (n & 7) * 4 + ((k & 7) >> 1);
        int reg = (k & 15) >> 3;
        uint32_t off = ((uint32_t)(gn * 8 + ks) * 32 + lane_t) * 8 + reg * 4;
        *(uint32_t*)(sm + NM_WH + off) = hi;
        *(uint32_t*)(sm + NM_WL + off) = lo;
    }
    __syncthreads();
    int nTn = (N_NODES + 63) >> 6;
    for (int tile = b0; tile < nTn; tile += 148) {
        #pragma unroll
        for (int j = 0; j < 8; j++) {
            int r = wid * 8 + j;
            int node = tile * 64 + r;
            int nodeC = node < N_NODES ? node : 0;
            int jr = r & 15, sl = r >> 4;
            #pragma unroll
            for (int kh = 0; kh < 2; kh++) {
                float2 v = *(const float2*)(x + (size_t)nodeC * XW + kh * 64 + 2 * lane);
                uint32_t hi, lo; split2(v.x, v.y, hi, lo);
                int lane_t = (jr & 7) * 4 + (lane & 3);
                int reg = (jr >> 3) | (((lane >> 2) & 1) << 1);
                int ks = kh * 4 + (lane >> 3);
                uint32_t off = ((uint32_t)(sl * 8 + ks) * 32 + lane_t) * 16 + reg * 4;
                *(uint32_t*)(sm + NM_AH + off) = hi;
                *(uint32_t*)(sm + NM_AL + off) = lo;
            }
        }
        __syncthreads();
        float acc[16][4];
        #pragma unroll
        for (int nt = 0; nt < 16; nt++)
            #pragma unroll
            for (int q = 0; q < 4; q++) acc[nt][q] = 0.f;
        #pragma unroll
        for (int ks = 0; ks < 8; ks++) {
            uint4 ah = *(const uint4*)(sm + NM_AH + ((uint32_t)(slot * 8 + ks) * 32 + lane) * 16);
            uint4 al = *(const uint4*)(sm + NM_AL + ((uint32_t)(slot * 8 + ks) * 32 + lane) * 16);
            #pragma unroll
            for (int nt = 0; nt < 16; nt++) {
                int gn = nh * 16 + nt;
                uint2 bh = *(const uint2*)(sm + NM_WH + ((uint32_t)(gn * 8 + ks) * 32 + lane) * 8);
                uint2 bl = *(const uint2*)(sm + NM_WL + ((uint32_t)(gn * 8 + ks) * 32 + lane) * 8);
                mma_bf16(acc[nt], ah, bh);
                mma_bf16(acc[nt], al, bh);
                mma_bf16(acc[nt], ah, bl);
            }
        }
        int r0 = slot * 16 + gid, r1 = r0 + 8;
        int n0 = tile * 64 + r0, n1 = tile * 64 + r1;
        #pragma unroll
        for (int nt = 0; nt < 16; nt++) {
            int c = nh * 128 + nt * 8 + tig * 2;
            if (n0 < N_NODES) *(float2*)(P + (size_t)n0 * H + c) = make_float2(acc[nt][0], acc[nt][1]);
            if (n1 < N_NODES) *(float2*)(P + (size_t)n1 * H + c) = make_float2(acc[nt][2], acc[nt][3]);
        }
        __syncthreads();
    }
}

// ---------------- fused edge MLP: GEMM1 + LN1 + GEMM2 + LN2 + scatter ----------------
// TILE = 32 edges, 512 threads, 1 CTA/SM
#define EF_EID 0
#define EF_ROW 128
#define EF_COL 256
#define EF_ATT 384
#define EF_ST  512
#define EF_B1  2560
#define EF_G1  3584
#define EF_BE1 4608
#define EF_B2  5632
#define EF_G2  6144
#define EF_BE2 6656
#define EF_A   7168    /* 16384 B: A1 frags (8KB hi + 8KB lo) then A2 frags (16KB) */
#define EF_W1H 23552
#define EF_W1L 56320
#define EF_W2H 89088
#define EF_W2L 154624
#define SMEM_EF 220160

__global__ void __launch_bounds__(512, 1) k_edge_fused(
    const int* __restrict__ ei, const float* __restrict__ eattr,
    const float* __restrict__ w1a, const float* __restrict__ b1a,
    const float* __restrict__ g1va, const float* __restrict__ be1va,
    const float* __restrict__ w2a, const float* __restrict__ b2a,
    const float* __restrict__ g2va, const float* __restrict__ be2va,
    const float* __restrict__ w1b, const float* __restrict__ b1b,
    const float* __restrict__ g1vb, const float* __restrict__ be1vb,
    const float* __restrict__ w2b, const float* __restrict__ b2b,
    const float* __restrict__ g2vb, const float* __restrict__ be2vb)
{
    extern __shared__ unsigned char sm[];
    int*   eidm  = (int*)(sm + EF_EID);
    int*   rowm  = (int*)(sm + EF_ROW);
    int*   colm  = (int*)(sm + EF_COL);
    float* attnm = (float*)(sm + EF_ATT);
    float* statm = (float*)(sm + EF_ST);
    float* b1s   = (float*)(sm + EF_B1);
    float* g1s   = (float*)(sm + EF_G1);
    float* be1s  = (float*)(sm + EF_BE1);
    float* b2s   = (float*)(sm + EF_B2);
    float* g2s   = (float*)(sm + EF_G2);
    float* be2s  = (float*)(sm + EF_BE2);

    int tid = threadIdx.x;
    int lane = tid & 31, wid = tid >> 5;
    int slot = wid & 1;        // edge group (16 edges)
    int nc   = wid >> 1;       // 0..7
    int gid  = lane >> 2, tig = lane & 3;
    int dir = blockIdx.x / 148;
    int b0  = blockIdx.x % 148;

    const float* w1full = dir ? w1b : w1a;
    const float* b1v  = dir ? b1b : b1a;
    const float* g1v  = dir ? g1vb : g1va;
    const float* be1v = dir ? be1vb : be1va;
    const float* w2   = dir ? w2b : w2a;
    const float* b2v  = dir ? b2b : b2a;
    const float* g2v  = dir ? g2vb : g2va;
    const float* be2v = dir ? be2vb : be2va;

    // stage W1bot frags (hi/lo), KS=4
    const float* wbg = w1full + 128 * H;
    for (int idx = tid; idx < 8192; idx += 512) {
        int k2i = idx >> 8, n = idx & 255;
        int k = 2 * k2i;
        float v0 = wbg[(size_t)k * H + n], v1 = wbg[(size_t)(k + 1) * H + n];
        uint32_t hi, lo; split2(v0, v1, hi, lo);
        int gn = n >> 3, ks = k >> 4;
        int lane_t = (n & 7) * 4 + ((k & 7) >> 1);
        int reg = (k & 15) >> 3;
        uint32_t off = ((uint32_t)(gn * 4 + ks) * 32 + lane_t) * 8 + reg * 4;
        *(uint32_t*)(sm + EF_W1H + off) = hi;
        *(uint32_t*)(sm + EF_W1L + off) = lo;
    }
    // stage W2 frags (hi/lo), KS=16
    for (int idx = tid; idx < 16384; idx += 512) {
        int k2i = idx >> 7, n = idx & 127;
        int k = 2 * k2i;
        float v0 = w2[(size_t)k * 128 + n], v1 = w2[(size_t)(k + 1) * 128 + n];
        uint32_t hi, lo; split2(v0, v1, hi, lo);
        int gn = n >> 3, ks = k >> 4;
        int lane_t = (n & 7) * 4 + ((k & 7) >> 1);
        int reg = (k & 15) >> 3;
        uint32_t off = ((uint32_t)(gn * 16 + ks) * 32 + lane_t) * 8 + reg * 4;
        *(uint32_t*)(sm + EF_W2H + off) = hi;
        *(uint32_t*)(sm + EF_W2L + off) = lo;
    }
    if (tid < 256) { b1s[tid] = b1v[tid]; g1s[tid] = g1v[tid]; be1s[tid] = be1v[tid]; }
    if (tid < 128) { b2s[tid] = b2v[tid]; g2s[tid] = g2v[tid]; be2s[tid] = be2v[tid]; }

    const int*   elist = dir ? g_elist1 : g_elist0;
    const float* Pd    = dir ? g_P1 : g_P0;
    int   cnt = g_ecnt[dir];
    float inv = 1.f / g_dirsum[dir];
    int   off_n = dir ? 0 : 128;
    int nT = (cnt + 31) >> 5;
    __syncthreads();

    for (int tile = b0; tile < nT; tile += 148) {
        if (tid < 32) {
            int li = tile * 32 + tid;
            bool valid = li < cnt;
            int ee = valid ? elist[li] : 0;
            eidm[tid]  = ee;
            rowm[tid]  = valid ? ei[ee] : -1;
            colm[tid]  = valid ? ei[N_EDGES + ee] : 0;
            attnm[tid] = valid ? g_expv[ee] * inv : 0.f;
        }
        __syncthreads();

        // stage A1 frags: 2 rows per warp
        #pragma unroll
        for (int j = 0; j < 2; j++) {
            int r = wid * 2 + j;
            int e = eidm[r];
            float2 v = *(const float2*)(eattr + (size_t)e * EATTR + 2 * lane);
            uint32_t hi, lo; split2(v.x, v.y, hi, lo);
            int jr = r & 15;
            int lane_t = (jr & 7) * 4 + (lane & 3);
            int reg = (jr >> 3) | (((lane >> 2) & 1) << 1);
            int ks = lane >> 3;
            uint32_t off = ((uint32_t)((r >> 4) * 4 + ks) * 32 + lane_t) * 16 + reg * 4;
            *(uint32_t*)(sm + EF_A + off) = hi;
            *(uint32_t*)(sm + EF_A + 4096 + off) = lo;
        }
        __syncthreads();

        // GEMM1: warp (slot, nc) = 16 edges x 32 cols, K=64
        float acc1[4][4];
        #pragma unroll
        for (int nt = 0; nt < 4; nt++)
            #pragma unroll
            for (int q = 0; q < 4; q++) acc1[nt][q] = 0.f;
        #pragma unroll
        for (int ks = 0; ks < 4; ks++) {
            uint4 ah = *(const uint4*)(sm + EF_A + ((uint32_t)(slot * 4 + ks) * 32 + lane) * 16);
            uint4 al = *(const uint4*)(sm + EF_A + 4096 + ((uint32_t)(slot * 4 + ks) * 32 + lane) * 16);
            #pragma unroll
            for (int nt = 0; nt < 4; nt++) {
                int gn = nc * 4 + nt;
                uint2 bh = *(const uint2*)(sm + EF_W1H + ((uint32_t)(gn * 4 + ks) * 32 + lane) * 8);
                uint2 bl = *(const uint2*)(sm + EF_W1L + ((uint32_t)(gn * 4 + ks) * 32 + lane) * 8);
                mma_bf16(acc1[nt], ah, bh);
                mma_bf16(acc1[nt], al, bh);
                mma_bf16(acc1[nt], ah, bl);
            }
        }

        // epilogue1: h = attn*(P + D1) + b1 ; LN1 partial stats
        int r0 = slot * 16 + gid, r1 = r0 + 8;
        float at0 = attnm[r0], at1 = attnm[r1];
        const float* P0 = Pd + (size_t)colm[r0] * H;
        const float* P1 = Pd + (size_t)colm[r1] * H;
        float sA = 0.f, qA = 0.f, sB = 0.f, qB = 0.f;
        #pragma unroll
        for (int nt = 0; nt < 4; nt++) {
            int c = nc * 32 + nt * 8 + tig * 2;
            float2 p0 = *(const float2*)(P0 + c);
            float2 p1 = *(const float2*)(P1 + c);
            float b10 = b1s[c], b11 = b1s[c + 1];
            acc1[nt][0] = at0 * (p0.x + acc1[nt][0]) + b10;
            acc1[nt][1] = at0 * (p0.y + acc1[nt][1]) + b11;
            acc1[nt][2] = at1 * (p1.x + acc1[nt][2]) + b10;
            acc1[nt][3] = at1 * (p1.y + acc1[nt][3]) + b11;
            sA += acc1[nt][0] + acc1[nt][1];
            qA += acc1[nt][0] * acc1[nt][0] + acc1[nt][1] * acc1[nt][1];
            sB += acc1[nt][2] + acc1[nt][3];
            qB += acc1[nt][2] * acc1[nt][2] + acc1[nt][3] * acc1[nt][3];
        }
        #pragma unroll
        for (int o = 1; o <= 2; o <<= 1) {
            sA += __shfl_xor_sync(0xffffffffu, sA, o);
            qA += __shfl_xor_sync(0xffffffffu, qA, o);
            sB += __shfl_xor_sync(0xffffffffu, sB, o);
            qB += __shfl_xor_sync(0xffffffffu, qB, o);
        }
        if (tig == 0) {
            statm[(r0 * 8 + nc) * 2]     = sA;
            statm[(r0 * 8 + nc) * 2 + 1] = qA;
            statm[(r1 * 8 + nc) * 2]     = sB;
            statm[(r1 * 8 + nc) * 2 + 1] = qB;
        }
        __syncthreads();     // also guarantees GEMM1 A reads are done before A2 overwrite
        float sTA = 0.f, qTA = 0.f, sTB = 0.f, qTB = 0.f;
        #pragma unroll
        for (int h = 0; h < 8; h++) {
            sTA += statm[(r0 * 8 + h) * 2];  qTA += statm[(r0 * 8 + h) * 2 + 1];
            sTB += statm[(r1 * 8 + h) * 2];  qTB += statm[(r1 * 8 + h) * 2 + 1];
        }
        float mA = sTA * (1.f / 256.f);
        float rA = rsqrtf(fmaxf(qTA * (1.f / 256.f) - mA * mA, 0.f) + LN_EPS);
        float mB = sTB * (1.f / 256.f);
        float rB = rsqrtf(fmaxf(qTB * (1.f / 256.f) - mB * mB, 0.f) + LN_EPS);

        // normalize + ReLU, write A2-hi frags; keep lo words in regs
        uint32_t loW[8];
        #pragma unroll
        for (int nt = 0; nt < 4; nt++) {
            int c = nc * 32 + nt * 8 + tig * 2;
            float u0 = fmaxf((acc1[nt][0] - mA) * rA * g1s[c]     + be1s[c],     0.f);
            float u1 = fmaxf((acc1[nt][1] - mA) * rA * g1s[c + 1] + be1s[c + 1], 0.f);
            float w0 = fmaxf((acc1[nt][2] - mB) * rB * g1s[c]     + be1s[c],     0.f);
            float w1 = fmaxf((acc1[nt][3] - mB) * rB * g1s[c + 1] + be1s[c + 1], 0.f);
            uint32_t hiA, loA, hiB, loB;
            split2(u0, u1, hiA, loA);
            split2(w0, w1, hiB, loB);
            int ks2 = nc * 2 + (nt >> 1);
            uint32_t base = ((uint32_t)(slot * 16 + ks2) * 32 + lane) * 16;
            int regA = (nt & 1) << 1;
            int regB = 1 | ((nt & 1) << 1);
            *(uint32_t*)(sm + EF_A + base + regA * 4) = hiA;
            *(uint32_t*)(sm + EF_A + base + regB * 4) = hiB;
            loW[nt * 2]     = loA;
            loW[nt * 2 + 1] = loB;
        }
        __syncthreads();

        // GEMM2 hi passes: Ah*Bh + Ah*Bl
        float acc2[2][4];
        #pragma unroll
        for (int nt = 0; nt < 2; nt++)
            #pragma unroll
            for (int q = 0; q < 4; q++) acc2[nt][q] = 0.f;
        #pragma unroll
        for (int ks = 0; ks < 16; ks++) {
            uint4 ah = *(const uint4*)(sm + EF_A + ((uint32_t)(slot * 16 + ks) * 32 + lane) * 16);
            #pragma unroll
            for (int nt = 0; nt < 2; nt++) {
                int gn = nc * 2 + nt;
                uint2 bh = *(const uint2*)(sm + EF_W2H + ((uint32_t)(gn * 16 + ks) * 32 + lane) * 8);
                uint2 bl = *(const uint2*)(sm + EF_W2L + ((uint32_t)(gn * 16 + ks) * 32 + lane) * 8);
                mma_bf16(acc2[nt], ah, bh);
                mma_bf16(acc2[nt], ah, bl);
            }
        }
        __syncthreads();

        // overwrite A region with Al frags
        #pragma unroll
        for (int nt = 0; nt < 4; nt++) {
            int ks2 = nc * 2 + (nt >> 1);
            uint32_t base = ((uint32_t)(slot * 16 + ks2) * 32 + lane) * 16;
            *(uint32_t*)(sm + EF_A + base + (((nt & 1) << 1)) * 4)       = loW[nt * 2];
            *(uint32_t*)(sm + EF_A + base + ((1 | ((nt & 1) << 1))) * 4) = loW[nt * 2 + 1];
        }
        __syncthreads();

        // GEMM2 lo pass: Al*Bh
        #pragma unroll
        for (int ks = 0; ks < 16; ks++) {
            uint4 al = *(const uint4*)(sm + EF_A + ((uint32_t)(slot * 16 + ks) * 32 + lane) * 16);
            #pragma unroll
            for (int nt = 0; nt < 2; nt++) {
                int gn = nc * 2 + nt;
                uint2 bh = *(const uint2*)(sm + EF_W2H + ((uint32_t)(gn * 16 + ks) * 32 + lane) * 8);
                mma_bf16(acc2[nt], al, bh);
            }
        }

        // epilogue2: + b2, LN2, ReLU, scatter
        float s2A = 0.f, q2A = 0.f, s2B = 0.f, q2B = 0.f;
        #pragma unroll
        for (int nt = 0; nt < 2; nt++) {
            int c = nc * 16 + nt * 8 + tig * 2;
            acc2[nt][0] += b2s[c];   acc2[nt][1] += b2s[c + 1];
            acc2[nt][2] += b2s[c];   acc2[nt][3] += b2s[c + 1];
            s2A += acc2[nt][0] + acc2[nt][1];
            q2A += acc2[nt][0] * acc2[nt][0] + acc2[nt][1] * acc2[nt][1];
            s2B += acc2[nt][2] + acc2[nt][3];
            q2B += acc2[nt][2] * acc2[nt][2] + acc2[nt][3] * acc2[nt][3];
        }
        #pragma unroll
        for (int o = 1; o <= 2; o <<= 1) {
            s2A += __shfl_xor_sync(0xffffffffu, s2A, o);
            q2A += __shfl_xor_sync(0xffffffffu, q2A, o);
            s2B += __shfl_xor_sync(0xffffffffu, s2B, o);
            q2B += __shfl_xor_sync(0xffffffffu, q2B, o);
        }
        if (tig == 0) {
            statm[(r0 * 8 + nc) * 2]     = s2A;
            statm[(r0 * 8 + nc) * 2 + 1] = q2A;
            statm[(r1 * 8 + nc) * 2]     = s2B;
            statm[(r1 * 8 + nc) * 2 + 1] = q2B;
        }
        __syncthreads();
        float fsA = 0.f, fqA = 0.f, fsB = 0.f, fqB = 0.f;
        #pragma unroll
        for (int h = 0; h < 8; h++) {
            fsA += statm[(r0 * 8 + h) * 2];  fqA += statm[(r0 * 8 + h) * 2 + 1];
            fsB += statm[(r1 * 8 + h) * 2];  fqB += statm[(r1 * 8 + h) * 2 + 1];
        }
        float m2A = fsA * (1.f / 128.f);
        float r2A = rsqrtf(fmaxf(fqA * (1.f / 128.f) - m2A * m2A, 0.f) + LN_EPS);
        float m2B = fsB * (1.f / 128.f);
        float r2B = rsqrtf(fmaxf(fqB * (1.f / 128.f) - m2B * m2B, 0.f) + LN_EPS);
        int rowA = rowm[r0], rowB = rowm[r1];
        #pragma unroll
        for (int nt = 0; nt < 2; nt++) {
            int c = nc * 16 + nt * 8 + tig * 2;
            if (rowA >= 0) {
                float v0 = fmaxf((acc2[nt][0] - m2A) * r2A * g2s[c]     + be2s[c],     0.f);
                float v1 = fmaxf((acc2[nt][1] - m2A) * r2A * g2s[c + 1] + be2s[c + 1], 0.f);
                atomicAdd(&g_flow[(size_t)rowA * 256 + off_n + c],     v0);
                atomicAdd(&g_flow[(size_t)rowA * 256 + off_n + c + 1], v1);
            }
            if (rowB >= 0) {
                float v0 = fmaxf((acc2[nt][2] - m2B) * r2B * g2s[c]     + be2s[c],     0.f);
                float v1 = fmaxf((acc2[nt][3] - m2B) * r2B * g2s[c + 1] + be2s[c + 1], 0.f);
                atomicAdd(&g_flow[(size_t)rowB * 256 + off_n + c],     v0);
                atomicAdd(&g_flow[(size_t)rowB * 256 + off_n + c + 1], v1);
            }
        }
        __syncthreads();
    }
}

// ---------------- k_final_a: U = relu(LN(flow @ node_w + b)) -> g_U ----------------
#define FA_ST  0
#define FA_NB  2048
#define FA_NG  2560
#define FA_NBE 3072
#define FA_AH  3584
#define FA_AL  36352
#define FA_WH  69120
#define FA_WL  134656
#define SMEM_FA 200192

__global__ void __launch_bounds__(512, 1) k_final_a(
    const float* __restrict__ node_w, const float* __restrict__ node_b,
    const float* __restrict__ node_g, const float* __restrict__ node_be)
{
    extern __shared__ unsigned char sm[];
    float* statm = (float*)(sm + FA_ST);
    float* nbs   = (float*)(sm + FA_NB);
    float* ngs   = (float*)(sm + FA_NG);
    float* nbes  = (float*)(sm + FA_NBE);

    int tid = threadIdx.x;
    int lane = tid & 31, wid = tid >> 5;
    int slot = wid & 3, nh = wid >> 2;
    int gid = lane >> 2, tig = lane & 3;

    for (int idx = tid; idx < 16384; idx += 512) {
        int k2i = idx >> 7, n = idx & 127;
        int k = 2 * k2i;
        float v0 = node_w[(size_t)k * 128 + n], v1 = node_w[(size_t)(k + 1) * 128 + n];
        uint32_t hi, lo; split2(v0, v1, hi, lo);
        int gn = n >> 3, ks = k >> 4;
        int lane_t = (n & 7) * 4 + ((k & 7) >> 1);
        int reg = (k & 15) >> 3;
        uint32_t off = ((uint32_t)(gn * 16 + ks) * 32 + lane_t) * 8 + reg * 4;
        *(uint32_t*)(sm + FA_WH + off) = hi;
        *(uint32_t*)(sm + FA_WL + off) = lo;
    }
    if (tid < 128) { nbs[tid] = node_b[tid]; ngs[tid] = node_g[tid]; nbes[tid] = node_be[tid]; }
    __syncthreads();

    int nTn = (N_NODES + 63) >> 6;
    for (int tile = blockIdx.x; tile < nTn; tile += gridDim.x) {
        #pragma unroll
        for (int j = 0; j < 4; j++) {
            int r = wid * 4 + j;
            int node = tile * 64 + r;
            int nodeC = node < N_NODES ? node : 0;
            int jr = r & 15, sl = r >> 4;
            #pragma unroll
            for (int kh = 0; kh < 4; kh++) {
                float2 v = *(const float2*)(g_flow + (size_t)nodeC * 256 + kh * 64 + 2 * lane);
                uint32_t hi, lo; split2(v.x, v.y, hi, lo);
                int lane_t = (jr & 7) * 4 + (lane & 3);
                int reg = (jr >> 3) | (((lane >> 2) & 1) << 1);
                int ks = kh * 4 + (lane >> 3);
                uint32_t off = ((uint32_t)(sl * 16 + ks) * 32 + lane_t) * 16 + reg * 4;
                *(uint32_t*)(sm + FA_AH + off) = hi;
                *(uint32_t*)(sm + FA_AL + off) = lo;
            }
        }
        __syncthreads();

        float acc[4][4];
        #pragma unroll
        for (int nt = 0; nt < 4; nt++)
            #pragma unroll
            for (int q = 0; q < 4; q++) acc[nt][q] = 0.f;
        #pragma unroll
        for (int ks = 0; ks < 16; ks++) {
            uint4 ah = *(const uint4*)(sm + FA_AH + ((uint32_t)(slot * 16 + ks) * 32 + lane) * 16);
            uint4 al = *(const uint4*)(sm + FA_AL + ((uint32_t)(slot * 16 + ks) * 32 + lane) * 16);
            #pragma unroll
            for (int nt = 0; nt < 4; nt++) {
                int gn = nh * 4 + nt;
                uint2 bh = *(const uint2*)(sm + FA_WH + ((uint32_t)(gn * 16 + ks) * 32 + lane) * 8);
                uint2 bl = *(const uint2*)(sm + FA_WL + ((uint32_t)(gn * 16 + ks) * 32 + lane) * 8);
                mma_bf16(acc[nt], ah, bh);
                mma_bf16(acc[nt], al, bh);
                mma_bf16(acc[nt], ah, bl);
            }
        }

        float sA = 0.f, qA = 0.f, sB = 0.f, qB = 0.f;
        #pragma unroll
        for (int nt = 0; nt < 4; nt++) {
            int c = nh * 32 + nt * 8 + tig * 2;
            acc[nt][0] += nbs[c];   acc[nt][1] += nbs[c + 1];
            acc[nt][2] += nbs[c];   acc[nt][3] += nbs[c + 1];
            sA += acc[nt][0] + acc[nt][1];
            qA += acc[nt][0] * acc[nt][0] + acc[nt][1] * acc[nt][1];
            sB += acc[nt][2] + acc[nt][3];
            qB += acc[nt][2] * acc[nt][2] + acc[nt][3] * acc[nt][3];
        }
        #pragma unroll
        for (int o = 1; o <= 2; o <<= 1) {
            sA += __shfl_xor_sync(0xffffffffu, sA, o);
            qA += __shfl_xor_sync(0xffffffffu, qA, o);
            sB += __shfl_xor_sync(0xffffffffu, sB, o);
            qB += __shfl_xor_sync(0xffffffffu, qB, o);
        }
        int e0 = slot * 16 + gid, e1 = e0 + 8;
        if (tig == 0) {
            statm[(e0 * 4 + nh) * 2]     = sA;
            statm[(e0 * 4 + nh) * 2 + 1] = qA;
            statm[(e1 * 4 + nh) * 2]     = sB;
            statm[(e1 * 4 + nh) * 2 + 1] = qB;
        }
        __syncthreads();
        float sTA = 0.f, qTA = 0.f, sTB = 0.f, qTB = 0.f;
        #pragma unroll
        for (int h = 0; h < 4; h++) {
            sTA += statm[(e0 * 4 + h) * 2];  qTA += statm[(e0 * 4 + h) * 2 + 1];
            sTB += statm[(e1 * 4 + h) * 2];  qTB += statm[(e1 * 4 + h) * 2 + 1];
        }
        float mA = sTA * (1.f / 128.f);
        float rAi = rsqrtf(fmaxf(qTA * (1.f / 128.f) - mA * mA, 0.f) + LN_EPS);
        float mB = sTB * (1.f / 128.f);
        float rBi = rsqrtf(fmaxf(qTB * (1.f / 128.f) - mB * mB, 0.f) + LN_EPS);
        int n0 = tile * 64 + e0, n1 = tile * 64 + e1;
        #pragma unroll
        for (int nt = 0; nt < 4; nt++) {
            int c = nh * 32 + nt * 8 + tig * 2;
            if (n0 < N_NODES) {
                float v0 = fmaxf((acc[nt][0] - mA) * rAi * ngs[c]     + nbes[c],     0.f);
                float v1 = fmaxf((acc[nt][1] - mA) * rAi * ngs[c + 1] + nbes[c + 1], 0.f);
                *(float2*)(g_U + (size_t)n0 * 128 + c) = make_float2(v0, v1);
            }
            if (n1 < N_NODES) {
                float v0 = fmaxf((acc[nt][2] - mB) * rBi * ngs[c]     + nbes[c],     0.f);
                float v1 = fmaxf((acc[nt][3] - mB) * rBi * ngs[c + 1] + nbes[c + 1], 0.f);
                *(float2*)(g_U + (size_t)n1 * 128 + c) = make_float2(v0, v1);
            }
        }
        __syncthreads();
    }
}

// ---------------- k_final_b ----------------
#define FB_ST  0
#define FB_SB  2048
#define FB_SG  2560
#define FB_SBE 3072
#define FB_AH  3584
#define FB_AL  19968
#define FB_WH  36352
#define FB_WL  69120
#define SMEM_FB 101888

__global__ void __launch_bounds__(512, 2) k_final_b(
    const float* __restrict__ x,
    const float* __restrict__ self_w, const float* __restrict__ self_b,
    const float* __restrict__ self_g, const float* __restrict__ self_be,
    float* __restrict__ out)
{
    extern __shared__ unsigned char sm[];
    float* statm = (float*)(sm + FB_ST);
    float* sbs   = (float*)(sm + FB_SB);
    float* sgs   = (float*)(sm + FB_SG);
    float* sbes  = (float*)(sm + FB_SBE);

    int tid = threadIdx.x;
    int lane = tid & 31, wid = tid >> 5;
    int slot = wid & 3, nh = wid >> 2;
    int gid = lane >> 2, tig = lane & 3;

    for (int idx = tid; idx < 8192; idx += 512) {
        int k2i = idx >> 7, n = idx & 127;
        int k = 2 * k2i;
        float v0 = self_w[(size_t)k * 128 + n], v1 = self_w[(size_t)(k + 1) * 128 + n];
        uint32_t hi, lo; split2(v0, v1, hi, lo);
        int gn = n >> 3, ks = k >> 4;
        int lane_t = (n & 7) * 4 + ((k & 7) >> 1);
        int reg = (k & 15) >> 3;
        uint32_t off = ((uint32_t)(gn * 8 + ks) * 32 + lane_t) * 8 + reg * 4;
        *(uint32_t*)(sm + FB_WH + off) = hi;
        *(uint32_t*)(sm + FB_WL + off) = lo;
    }
    if (tid < 128) { sbs[tid] = self_b[tid]; sgs[tid] = self_g[tid]; sbes[tid] = self_be[tid]; }
    __syncthreads();

    int nTn = (N_NODES + 63) >> 6;
    for (int tile = blockIdx.x; tile < nTn; tile += gridDim.x) {
        #pragma unroll
        for (int j = 0; j < 4; j++) {
            int r = wid * 4 + j;
            int node = tile * 64 + r;
            int nodeC = node < N_NODES ? node : 0;
            int jr = r & 15, sl = r >> 4;
            #pragma unroll
            for (int kh = 0; kh < 2; kh++) {
                float2 v = *(const float2*)(x + (size_t)nodeC * XW + kh * 64 + 2 * lane);
                uint32_t hi, lo; split2(v.x, v.y, hi, lo);
                int lane_t = (jr & 7) * 4 + (lane & 3);
                int reg = (jr >> 3) | (((lane >> 2) & 1) << 1);
                int ks = kh * 4 + (lane >> 3);
                uint32_t off = ((uint32_t)(sl * 8 + ks) * 32 + lane_t) * 16 + reg * 4;
                *(uint32_t*)(sm + FB_AH + off) = hi;
                *(uint32_t*)(sm + FB_AL + off) = lo;
            }
        }
        __syncthreads();

        float acc[4][4];
        #pragma unroll
        for (int nt = 0; nt < 4; nt++)
            #pragma unroll
            for (int q = 0; q < 4; q++) acc[nt][q] = 0.f;
        #pragma unroll
        for (int ks = 0; ks < 8; ks++) {
            uint4 ah = *(const uint4*)(sm + FB_AH + ((uint32_t)(slot * 8 + ks) * 32 + lane) * 16);
            uint4 al = *(const uint4*)(sm + FB_AL + ((uint32_t)(slot * 8 + ks) * 32 + lane) * 16);
            #pragma unroll
            for (int nt = 0; nt < 4; nt++) {
                int gn = nh * 4 + nt;
                uint2 bh = *(const uint2*)(sm + FB_WH + ((uint32_t)(gn * 8 + ks) * 32 + lane) * 8);
                uint2 bl = *(const uint2*)(sm + FB_WL + ((uint32_t)(gn * 8 + ks) * 32 + lane) * 8);
                mma_bf16(acc[nt], ah, bh);
                mma_bf16(acc[nt], al, bh);
                mma_bf16(acc[nt], ah, bl);
            }
        }

        float sA = 0.f, qA = 0.f, sB = 0.f, qB = 0.f;
        #pragma unroll
        for (int nt = 0; nt < 4; nt++) {
            int c = nh * 32 + nt * 8 + tig * 2;
            acc[nt][0] += sbs[c];   acc[nt][1] += sbs[c + 1];
            acc[nt][2] += sbs[c];   acc[nt][3] += sbs[c + 1];
            sA += acc[nt][0] + acc[nt][1];
            qA += acc[nt][0] * acc[nt][0] + acc[nt][1] * acc[nt][1];
            sB += acc[nt][2] + acc[nt][3];
            qB += acc[nt][2] * acc[nt][2] + acc[nt][3] * acc[nt][3];
        }
        #pragma unroll
        for (int o = 1; o <= 2; o <<= 1) {
            sA += __shfl_xor_sync(0xffffffffu, sA, o);
            qA += __shfl_xor_sync(0xffffffffu, qA, o);
            sB += __shfl_xor_sync(0xffffffffu, sB, o);
            qB += __shfl_xor_sync(0xffffffffu, qB, o);
        }
        int e0 = slot * 16 + gid, e1 = e0 + 8;
        if (tig == 0) {
            statm[(e0 * 4 + nh) * 2]     = sA;
            statm[(e0 * 4 + nh) * 2 + 1] = qA;
            statm[(e1 * 4 + nh) * 2]     = sB;
            statm[(e1 * 4 + nh) * 2 + 1] = qB;
        }
        __syncthreads();
        float sTA = 0.f, qTA = 0.f, sTB = 0.f, qTB = 0.f;
        #pragma unroll
        for (int h = 0; h < 4; h++) {
            sTA += statm[(e0 * 4 + h) * 2];  qTA += statm[(e0 * 4 + h) * 2 + 1];
            sTB += statm[(e1 * 4 + h) * 2];  qTB += statm[(e1 * 4 + h) * 2 + 1];
        }
        float mA = sTA * (1.f / 128.f);
        float rAi = rsqrtf(fmaxf(qTA * (1.f / 128.f) - mA * mA, 0.f) + LN_EPS);
        float mB = sTB * (1.f / 128.f);
        float rBi = rsqrtf(fmaxf(qTB * (1.f / 128.f) - mB * mB, 0.f) + LN_EPS);
        int n0 = tile * 64 + e0, n1 = tile * 64 + e1;
        #pragma unroll
        for (int nt = 0; nt < 4; nt++) {
            int c = nh * 32 + nt * 8 + tig * 2;
            if (n0 < N_NODES) {
                float2 uv = *(const float2*)(g_U + (size_t)n0 * 128 + c);
                float v0 = fmaxf((acc[nt][0] - mA) * rAi * sgs[c]     + sbes[c],     0.f) + uv.x;
                float v1 = fmaxf((acc[nt][1] - mA) * rAi * sgs[c + 1] + sbes[c + 1], 0.f) + uv.y;
                *(float2*)(out + (size_t)n0 * XW + c) = make_float2(v0, v1);
            }
            if (n1 < N_NODES) {
                float2 uv = *(const float2*)(g_U + (size_t)n1 * 128 + c);
                float v0 = fmaxf((acc[nt][2] - mB) * rBi * sgs[c]     + sbes[c],     0.f) + uv.x;
                float v1 = fmaxf((acc[nt][3] - mB) * rBi * sgs[c + 1] + sbes[c + 1], 0.f) + uv.y;
                *(float2*)(out + (size_t)n1 * XW + c) = make_float2(v0, v1);
            }
        }
        for (int idx = tid; idx < 64 * 32; idx += 512) {
            int r = idx >> 5, j = idx & 31;
            int n = tile * 64 + r;
            if (n < N_NODES)
                out[(size_t)n * XW + 128 + j] = x[(size_t)n * XW + 128 + j];
        }
        __syncthreads();
    }
}

extern "C" void kernel_launch(void* const* d_in, const int* in_sizes, int n_in,
                              void* d_out, int out_size) {
    const float* x      = (const float*)d_in[0];
    const int*   ei     = (const int*)d_in[1];
    const float* eattr  = (const float*)d_in[2];
    const float* w_att  = (const float*)d_in[3];
    const float* b_att  = (const float*)d_in[4];
    const float* d2t_w1 = (const float*)d_in[5];
    const float* d2t_b1 = (const float*)d_in[6];
    const float* d2t_g1 = (const float*)d_in[7];
    const float* d2t_be1= (const float*)d_in[8];
    const float* d2t_w2 = (const float*)d_in[9];
    const float* d2t_b2 = (const float*)d_in[10];
    const float* d2t_g2 = (const float*)d_in[11];
    const float* d2t_be2= (const float*)d_in[12];
    const float* t2d_w1 = (const float*)d_in[13];
    const float* t2d_b1 = (const float*)d_in[14];
    const float* t2d_g1 = (const float*)d_in[15];
    const float* t2d_be1= (const float*)d_in[16];
    const float* t2d_w2 = (const float*)d_in[17];
    const float* t2d_b2 = (const float*)d_in[18];
    const float* t2d_g2 = (const float*)d_in[19];
    const float* t2d_be2= (const float*)d_in[20];
    const float* node_w = (const float*)d_in[21];
    const float* node_b = (const float*)d_in[22];
    const float* node_g = (const float*)d_in[23];
    const float* node_be= (const float*)d_in[24];
    const float* self_w = (const float*)d_in[25];
    const float* self_b = (const float*)d_in[26];
    const float* self_g = (const float*)d_in[27];
    const float* self_be= (const float*)d_in[28];
    float* out = (float*)d_out;

    cudaFuncSetAttribute(k_node_mma,   cudaFuncAttributeMaxDynamicSharedMemorySize, SMEM_NM);
    cudaFuncSetAttribute(k_edge_fused, cudaFuncAttributeMaxDynamicSharedMemorySize, SMEM_EF);
    cudaFuncSetAttribute(k_final_a,    cudaFuncAttributeMaxDynamicSharedMemorySize, SMEM_FA);
    cudaFuncSetAttribute(k_final_b,    cudaFuncAttributeMaxDynamicSharedMemorySize, SMEM_FB);

    int initThreads = (int)((size_t)N_NODES * 256 / 4);
    k_init_att<<<(initThreads + 255) / 256, 256>>>(x, w_att);
    k_node_mma<<<296, 256, SMEM_NM>>>(x, d2t_w1, t2d_w1);
    k_sumexp<<<(N_EDGES + 255) / 256, 256>>>(ei, b_att);
    k_edge_fused<<<296, 512, SMEM_EF>>>(ei, eattr,
        d2t_w1, d2t_b1, d2t_g1, d2t_be1, d2t_w2, d2t_b2, d2t_g2, d2t_be2,
        t2d_w1, t2d_b1, t2d_g1, t2d_be1, t2d_w2, t2d_b2, t2d_g2, t2d_be2);
    k_final_a<<<148, 512, SMEM_FA>>>(node_w, node_b, node_g, node_be);
    k_final_b<<<296, 512, SMEM_FB>>>(x, self_w, self_b, self_g, self_be, out);
}